// round 12
// baseline (speedup 1.0000x reference)
#include <cuda_runtime.h>
#include <math.h>

#define Bb 4
#define Ss 1024
#define Dd 512
#define Hh 8
#define DHd 64
#define SST 1034   // sbuf row stride (floats): conflict-free for 2/4-row strides

typedef unsigned long long ull;

__device__ __constant__ float kScale = 0.044194173824159216f; // 1/sqrt(512)

// ---- packed f32x2 helpers (sm_103a) ----
__device__ __forceinline__ ull pk2(float x, float y) {
    ull r; asm("mov.b64 %0, {%1, %2};" : "=l"(r) : "f"(x), "f"(y)); return r;
}
__device__ __forceinline__ ull splat2(float x) {
    ull r; asm("mov.b64 %0, {%1, %1};" : "=l"(r) : "f"(x)); return r;
}
__device__ __forceinline__ float lo2(ull v) { return __uint_as_float((unsigned)v); }
__device__ __forceinline__ float hi2(ull v) { return __uint_as_float((unsigned)(v >> 32)); }
__device__ __forceinline__ void fma2(ull& d, ull a, ull b) {
    asm("fma.rn.f32x2 %0, %1, %2, %0;" : "+l"(d) : "l"(a), "l"(b));
}
__device__ __forceinline__ float red2(ull v) { return lo2(v) + hi2(v); }

__device__ __forceinline__ unsigned smem_u32(const void* p) {
    return (unsigned)__cvta_generic_to_shared(p);
}
// volatile: real memory reads — must not be hoisted across C++ smem stores /
// __syncthreads() (R8 failure root cause).
__device__ __forceinline__ void lds2x64(ull& a, ull& b, unsigned addr) {
    asm volatile("ld.shared.v2.b64 {%0,%1}, [%2];" : "=l"(a), "=l"(b) : "r"(addr));
}
__device__ __forceinline__ float lds32(unsigned addr) {
    float v; asm volatile("ld.shared.f32 %0, [%1];" : "=f"(v) : "r"(addr)); return v;
}

// ---- tf32 mma helpers ----
__device__ __forceinline__ unsigned cvt_tf32(float x) {
    unsigned r; asm("cvt.rna.tf32.f32 %0, %1;" : "=r"(r) : "f"(x)); return r;
}
__device__ __forceinline__ void mma_tf32(
    float& d0, float& d1, float& d2, float& d3,
    unsigned a0, unsigned a1, unsigned a2, unsigned a3,
    unsigned b0, unsigned b1)
{
    asm volatile(
        "mma.sync.aligned.m16n8k8.row.col.f32.tf32.tf32.f32 "
        "{%0,%1,%2,%3}, {%4,%5,%6,%7}, {%8,%9}, {%0,%1,%2,%3};"
        : "+f"(d0), "+f"(d1), "+f"(d2), "+f"(d3)
        : "r"(a0), "r"(a1), "r"(a2), "r"(a3), "r"(b0), "r"(b1));
}

// scratch: 11 chunks of B*S*D floats
#define CHUNK ((size_t)Bb * Ss * Dd)  // 2097152
__device__ float g_scratch[CHUNK * 11];

#define OFF_QU1 (0 * CHUNK)
#define OFF_QV1 (1 * CHUNK)
#define OFF_K1  (2 * CHUNK)
#define OFF_V1  (3 * CHUNK)
#define OFF_QU2 (4 * CHUNK)
#define OFF_QV2 (5 * CHUNK)
#define OFF_K2  (6 * CHUNK)
#define OFF_V2  (7 * CHUNK)
#define OFF_POS (8 * CHUNK)
#define OFF_CTX1 (9 * CHUNK)
#define OFF_CTX2 (10 * CHUNK)

// d_out offsets (floats)
#define OFF_CTX1OUT ((size_t)0)
#define OFF_ATTN1   ((size_t)2097152)
#define OFF_CTX2OUT ((size_t)35651584)
#define OFF_ATTN2   ((size_t)37748736)

// ---------------------------------------------------------------------------
// Batched SGEMM (unchanged)
// ---------------------------------------------------------------------------
struct GDesc {
    const float* A; const float* W; const float* bias;
    float* d0; float* d1;
    const float* e0; const float* e1;
    long long mode;
};
struct GDescArr { GDesc g[8]; };

__global__ __launch_bounds__(256, 2)
void sgemm_batch(GDescArr P)
{
    GDesc gd = P.g[blockIdx.z];
    __shared__ float As[2][8][128];
    __shared__ float Bs[2][8][128];
    int tid = threadIdx.x;
    int tx = tid & 15, ty = tid >> 4;
    int bx = blockIdx.x, by = blockIdx.y;

    ull acc[8][4];
#pragma unroll
    for (int i = 0; i < 8; i++)
#pragma unroll
        for (int j = 0; j < 4; j++) acc[i][j] = 0ull;

    int arow = tid >> 1, ahalf = tid & 1;
    int bkr = tid >> 5, bn = tid & 31;
    const float* Aptr = gd.A + (size_t)(by * 128 + arow) * 512 + ahalf * 4;
    const float* Wptr = gd.W + (size_t)bkr * 512 + bx * 128 + bn * 4;

    float4 av = *(const float4*)(Aptr);
    float4 wv = *(const float4*)(Wptr);
    As[0][ahalf * 4 + 0][arow] = av.x;
    As[0][ahalf * 4 + 1][arow] = av.y;
    As[0][ahalf * 4 + 2][arow] = av.z;
    As[0][ahalf * 4 + 3][arow] = av.w;
    *(float4*)&Bs[0][bkr][bn * 4] = wv;
    __syncthreads();

#pragma unroll 1
    for (int kk = 0; kk < 64; kk++) {
        int buf = kk & 1;
        if (kk < 63) {
            av = *(const float4*)(Aptr + (kk + 1) * 8);
            wv = *(const float4*)(Wptr + (size_t)(kk + 1) * 8 * 512);
        }
#pragma unroll
        for (int k = 0; k < 8; k++) {
            float4 a0 = *(const float4*)&As[buf][k][ty * 8];
            float4 a1 = *(const float4*)&As[buf][k][ty * 8 + 4];
            unsigned bs_u = smem_u32(&Bs[buf][k][tx * 8]);
            ull bb[4];
            lds2x64(bb[0], bb[1], bs_u);
            lds2x64(bb[2], bb[3], bs_u + 16);
            ull aa[8] = { splat2(a0.x), splat2(a0.y), splat2(a0.z), splat2(a0.w),
                          splat2(a1.x), splat2(a1.y), splat2(a1.z), splat2(a1.w) };
#pragma unroll
            for (int i = 0; i < 8; i++)
#pragma unroll
                for (int j = 0; j < 4; j++) fma2(acc[i][j], aa[i], bb[j]);
        }
        if (kk < 63) {
            int nb = buf ^ 1;
            As[nb][ahalf * 4 + 0][arow] = av.x;
            As[nb][ahalf * 4 + 1][arow] = av.y;
            As[nb][ahalf * 4 + 2][arow] = av.z;
            As[nb][ahalf * 4 + 3][arow] = av.w;
            *(float4*)&Bs[nb][bkr][bn * 4] = wv;
            __syncthreads();
        }
    }

    int mode = (int)gd.mode;
#pragma unroll
    for (int i = 0; i < 8; i++) {
        int gr = by * 128 + ty * 8 + i;
#pragma unroll
        for (int jj = 0; jj < 4; jj++) {
#pragma unroll
            for (int half = 0; half < 2; half++) {
                int j = 2 * jj + half;
                int gc = bx * 128 + tx * 8 + j;
                float v = (half ? hi2(acc[i][jj]) : lo2(acc[i][jj]))
                          + (gd.bias ? gd.bias[gc] : 0.f);
                if (mode == 0) {
                    gd.d0[(size_t)gr * 512 + gc] = v;
                } else {
                    int h = gc >> 6, d = gc & 63;
                    int bI = gr >> 10, sI = gr & 1023;
                    size_t off = (((size_t)(bI * Hh + h) * Ss + sI) * DHd + d);
                    if (mode == 1) {
                        gd.d0[off] = v;
                    } else {
                        gd.d0[off] = v + gd.e0[gc];
                        gd.d1[off] = v + gd.e1[gc];
                    }
                }
            }
        }
    }
}

// ---------------------------------------------------------------------------
// Fused attention kernel (512 threads, ~111 KB smem -> 2 blocks/SM).
//  pass 1: sbuf = content scores via tf32 mma.sync (16x8x8 tiles)
//  pass 2: sbuf += pos scores (tf32 mma) scattered through rel-shift bijection
//  register softmax; attn to gmem; phase E: ctx = sbuf @ V (exact fp32)
// q buffers hold tf32-bit patterns (valid f32) -> raw u32 fragment loads.
// ---------------------------------------------------------------------------
__global__ __launch_bounds__(512, 2)
void attn_kernel(float* __restrict__ scratch,
                 const unsigned char* __restrict__ maskg,
                 float* __restrict__ out)
{
    extern __shared__ float sm[];
    float* qu   = sm;                 // [16][68] tf32-bit u32 (as float storage)
    float* qv   = sm + 1088;          // [17][68] tf32-bit u32
    float* kb   = sm + 2244;          // [128][68] = 8704 (tile / reduce buffer)
    float* sbuf = sm + 10948;         // [16][SST] = 16544 (scores -> probs)
    unsigned char* msk = (unsigned char*)(sm + 27492); // 1024 B

    int tid = threadIdx.x;
    int lane = tid & 31, w = tid >> 5;   // w 0..15
    int tile = blockIdx.x;   // 0..63
    int h = blockIdx.y;      // 0..7
    int bz = blockIdx.z;     // 0..7
    int bI = bz >> 1, st = bz & 1;

    const float* QUg = scratch + (st ? OFF_QU2 : OFF_QU1);
    const float* QVg = scratch + (st ? OFF_QV2 : OFF_QV1);
    const float* Kg  = scratch + (st ? OFF_K2  : OFF_K1);
    const float* Vg  = scratch + (st ? OFF_V2  : OFF_V1);
    const float* Pg  = scratch + OFF_POS;
    float* CTXg = scratch + (st ? OFF_CTX2 : OFF_CTX1);

    size_t bh = (size_t)(bI * Hh + h) * Ss * DHd;

    unsigned* quw = (unsigned*)qu;
    unsigned* qvw = (unsigned*)qv;

    // ---- phase 0: q loads pre-converted to tf32 bits, mask ----
#pragma unroll
    for (int it = 0; it < 2; it++) {
        int idx = it * 512 + tid;                // 0..1023
        int r = idx >> 6, d = idx & 63;
        quw[r * 68 + d] = cvt_tf32(QUg[bh + (size_t)(tile * 16 + r) * 64 + d]);
    }
#pragma unroll
    for (int it = 0; it < 3; it++) {
        int idx = it * 512 + tid;
        if (idx < 1088) {
            int r = idx >> 6, d = idx & 63;
            int gi = tile * 16 + r;
            if (gi > Ss - 1) gi = Ss - 1;        // row16 of last tile: blocked below
            qvw[r * 68 + d] = cvt_tf32(QVg[bh + (size_t)gi * 64 + d]);
        }
    }
    {
        const unsigned char* mrow = maskg + (size_t)bI * Ss;
#pragma unroll
        for (int it = 0; it < 2; it++) {
            int idx = it * 512 + tid;
            msk[idx] = mrow[idx];
        }
    }
    __syncthreads();

    unsigned qv_u = smem_u32(qv);
    unsigned kb_u = smem_u32(kb);

    int g  = lane >> 2;   // mma group 0..7
    int tg = lane & 3;    // thread-in-group 0..3

    // ================= pass 1: content -> sbuf (tf32 mma) =================
    {
        float4 fl[4];
#pragma unroll
        for (int it = 0; it < 4; it++) {
            int idx = it * 512 + tid; int s_ = idx >> 4, ds = idx & 15;
            fl[it] = *(const float4*)(Kg + bh + (size_t)s_ * 64 + ds * 4);
        }
#pragma unroll 1
        for (int c = 0; c < 8; c++) {
#pragma unroll
            for (int it = 0; it < 4; it++) {
                int idx = it * 512 + tid; int s_ = idx >> 4, ds = idx & 15;
                *(float4*)(kb + s_ * 68 + ds * 4) = fl[it];
            }
            __syncthreads();
            if (c < 7) {
#pragma unroll
                for (int it = 0; it < 4; it++) {
                    int idx = it * 512 + tid; int s_ = idx >> 4, ds = idx & 15;
                    fl[it] = *(const float4*)(Kg + bh
                                  + (size_t)((c + 1) * 128 + s_) * 64 + ds * 4);
                }
            }
            float d0 = 0.f, d1 = 0.f, d2 = 0.f, d3 = 0.f;
            const float* kcol = kb + (w * 8 + g) * 68;
#pragma unroll
            for (int ks = 0; ks < 8; ks++) {
                unsigned a0 = quw[g * 68 + ks * 8 + tg];
                unsigned a1 = quw[(g + 8) * 68 + ks * 8 + tg];
                unsigned a2 = quw[g * 68 + ks * 8 + tg + 4];
                unsigned a3 = quw[(g + 8) * 68 + ks * 8 + tg + 4];
                unsigned b0 = cvt_tf32(kcol[ks * 8 + tg]);
                unsigned b1 = cvt_tf32(kcol[ks * 8 + tg + 4]);
                mma_tf32(d0, d1, d2, d3, a0, a1, a2, a3, b0, b1);
            }
            int col = c * 128 + w * 8 + 2 * tg;
            *(float2*)&sbuf[g * SST + col] = make_float2(d0, d1);
            *(float2*)&sbuf[(g + 8) * SST + col] = make_float2(d2, d3);
            __syncthreads();
        }
    }

    // ================= pass 2: pos scatter-add into sbuf (tf32 mma) ========
    // raw pos[local row j, col cg], gg = tile*16+j:
    //   cg >= S-1-gg : sbuf[j][cg+gg+1-S] += v
    //   else (j>0)   : sbuf[j-1][cg+gg+1] += v
    {
        float4 fl[4];
#pragma unroll
        for (int it = 0; it < 4; it++) {
            int idx = it * 512 + tid; int s_ = idx >> 4, ds = idx & 15;
            fl[it] = *(const float4*)(Pg + bh + (size_t)s_ * 64 + ds * 4);
        }
#pragma unroll 1
        for (int c = 0; c < 8; c++) {
#pragma unroll
            for (int it = 0; it < 4; it++) {
                int idx = it * 512 + tid; int s_ = idx >> 4, ds = idx & 15;
                *(float4*)(kb + s_ * 68 + ds * 4) = fl[it];
            }
            __syncthreads();
            if (c < 7) {
#pragma unroll
                for (int it = 0; it < 4; it++) {
                    int idx = it * 512 + tid; int s_ = idx >> 4, ds = idx & 15;
                    fl[it] = *(const float4*)(Pg + bh
                                  + (size_t)((c + 1) * 128 + s_) * 64 + ds * 4);
                }
            }
            float d0 = 0.f, d1 = 0.f, d2 = 0.f, d3 = 0.f;
            const float* pcol = kb + (w * 8 + g) * 68;
#pragma unroll
            for (int ks = 0; ks < 8; ks++) {
                unsigned a0 = qvw[g * 68 + ks * 8 + tg];
                unsigned a1 = qvw[(g + 8) * 68 + ks * 8 + tg];
                unsigned a2 = qvw[g * 68 + ks * 8 + tg + 4];
                unsigned a3 = qvw[(g + 8) * 68 + ks * 8 + tg + 4];
                unsigned b0 = cvt_tf32(pcol[ks * 8 + tg]);
                unsigned b1 = cvt_tf32(pcol[ks * 8 + tg + 4]);
                mma_tf32(d0, d1, d2, d3, a0, a1, a2, a3, b0, b1);
            }
            int cg0 = c * 128 + w * 8 + 2 * tg;
            float vv[4] = { d0, d1, d2, d3 };
            int rr[4]   = { g, g, g + 8, g + 8 };
            int cc[4]   = { cg0, cg0 + 1, cg0, cg0 + 1 };
#pragma unroll
            for (int j = 0; j < 4; j++) {
                int row = rr[j], cg = cc[j];
                int gg = tile * 16 + row;
                bool condA = (cg >= Ss - 1 - gg);
                int addr = condA ? (row * SST + (cg + gg + 1 - Ss))
                                 : ((row - 1) * SST + (cg + gg + 1));
                if (condA || row > 0) sbuf[addr] += vv[j];
            }
            if (w < 4) {   // extra pos row 16 -> contributes only to row 15 (fp32)
                int col16 = w * 32 + lane;
                unsigned q16_u = qv_u + 16u * 272;
                unsigned pc_u = kb_u + (unsigned)col16 * 272;
                ull a = 0;
#pragma unroll
                for (int dq = 0; dq < 16; dq++) {
                    ull q01, q23; lds2x64(q01, q23, q16_u + dq * 16);
                    ull p01, p23; lds2x64(p01, p23, pc_u + dq * 16);
                    fma2(a, q01, p01); fma2(a, q23, p23);
                }
                int g16 = tile * 16 + 16;
                int cg16 = c * 128 + col16;
                if (g16 <= Ss - 1 && cg16 <= Ss - 2 - g16)
                    sbuf[15 * SST + (cg16 + g16 + 1)] += red2(a);
            }
            __syncthreads();
        }
    }

    // ---- softmax (warp = 1 row), register array ----
    int r = w;
    int ig = tile * 16 + r;
    float s[32];

    float mx = -1e30f;
#pragma unroll
    for (int jp = 0; jp < 32; jp++) {
        int t = jp * 32 + lane;
        float sc = sbuf[r * SST + t] * kScale;
        if (msk[t]) sc = -1e9f;
        s[jp] = sc;
        mx = fmaxf(mx, sc);
    }
#pragma unroll
    for (int o = 16; o > 0; o >>= 1)
        mx = fmaxf(mx, __shfl_xor_sync(0xffffffffu, mx, o));
    float sum = 0.f;
#pragma unroll
    for (int jp = 0; jp < 32; jp++) {
        float e = __expf(s[jp] - mx); s[jp] = e; sum += e;
    }
#pragma unroll
    for (int o = 16; o > 0; o >>= 1)
        sum += __shfl_xor_sync(0xffffffffu, sum, o);
    float inv = 1.f / sum;

    __syncthreads();

    size_t aout = (st ? OFF_ATTN2 : OFF_ATTN1) + ((size_t)(bI * Hh + h) * Ss) * Ss;
#pragma unroll
    for (int jp = 0; jp < 32; jp++) {
        int t = jp * 32 + lane;
        float p = s[jp] * inv;
        sbuf[r * SST + t] = p;
        out[aout + (size_t)ig * Ss + t] = p;
    }
    __syncthreads();

    // ---- phase E: ctx = sbuf(probs) @ V (exact fp32); kb tile/reduce buf ----
    {
        int dpg = tid & 15;        // d0 = dpg*4
        int rg  = (tid >> 4) & 7;  // rows rg*2, rg*2+1
        int tq  = tid >> 7;        // t-quarter 0..3
        int d0 = dpg * 4;

        ull e00 = 0, e01 = 0, e10 = 0, e11 = 0;

        float4 fl[4];
#pragma unroll
        for (int it = 0; it < 4; it++) {
            int idx = it * 512 + tid; int s_ = idx >> 4, ds = idx & 15;
            fl[it] = *(const float4*)(Vg + bh + (size_t)s_ * 64 + ds * 4);
        }
        unsigned pr_base = smem_u32(sbuf) + (unsigned)(rg * 2 * SST + tq * 32) * 4;
#pragma unroll 1
        for (int c = 0; c < 8; c++) {
#pragma unroll
            for (int it = 0; it < 4; it++) {
                int idx = it * 512 + tid; int s_ = idx >> 4, ds = idx & 15;
                *(float4*)(kb + s_ * 68 + ds * 4) = fl[it];
            }
            __syncthreads();
            if (c < 7) {
#pragma unroll
                for (int it = 0; it < 4; it++) {
                    int idx = it * 512 + tid; int s_ = idx >> 4, ds = idx & 15;
                    fl[it] = *(const float4*)(Vg + bh
                                  + (size_t)((c + 1) * 128 + s_) * 64 + ds * 4);
                }
            }
            unsigned v_base = kb_u + (unsigned)(tq * 32) * 272 + d0 * 4;
            unsigned pr_u = pr_base + (unsigned)(c * 128) * 4;
#pragma unroll
            for (int tt = 0; tt < 32; tt++) {
                ull v01, v23; lds2x64(v01, v23, v_base + tt * 272);
                float a0 = lds32(pr_u + tt * 4);
                float a1 = lds32(pr_u + tt * 4 + SST * 4);
                ull sx;
                sx = splat2(a0); fma2(e00, sx, v01); fma2(e01, sx, v23);
                sx = splat2(a1); fma2(e10, sx, v01); fma2(e11, sx, v23);
            }
            __syncthreads();
        }

        // partial sums -> kb[tq][row*64+d] (kb free now), reduce 4 quarters
        {
            float* red = kb + tq * 1024 + (rg * 2) * 64 + d0;
            float4 v0; v0.x = lo2(e00); v0.y = hi2(e00); v0.z = lo2(e01); v0.w = hi2(e01);
            float4 v1; v1.x = lo2(e10); v1.y = hi2(e10); v1.z = lo2(e11); v1.w = hi2(e11);
            *(float4*)(red) = v0;
            *(float4*)(red + 64) = v1;
        }
        __syncthreads();
        if (tid < 256) {
            int o = tid * 4;                  // 0..1023, 4 outputs per thread
            int row = o >> 6, dd = o & 63;
            float4 p0 = *(const float4*)(kb + 0 * 1024 + o);
            float4 p1 = *(const float4*)(kb + 1 * 1024 + o);
            float4 p2 = *(const float4*)(kb + 2 * 1024 + o);
            float4 p3 = *(const float4*)(kb + 3 * 1024 + o);
            float4 rr;
            rr.x = (p0.x + p1.x) + (p2.x + p3.x);
            rr.y = (p0.y + p1.y) + (p2.y + p3.y);
            rr.z = (p0.z + p1.z) + (p2.z + p3.z);
            rr.w = (p0.w + p1.w) + (p2.w + p3.w);
            int gi = tile * 16 + row;
            *(float4*)(CTXg + ((size_t)(bI * Ss + gi)) * Dd + h * DHd + dd) = rr;
        }
    }
}

// ---------------------------------------------------------------------------
extern "C" void kernel_launch(void* const* d_in, const int* in_sizes, int n_in,
                              void* d_out, int out_size)
{
    const float* x1  = (const float*)d_in[0];
    const float* x2  = (const float*)d_in[1];
    const float* pe  = (const float*)d_in[2];
    const unsigned char* mask = (const unsigned char*)d_in[3];
    const float* Wq  = (const float*)d_in[4];
    const float* bq  = (const float*)d_in[5];
    const float* Wk  = (const float*)d_in[6];
    const float* bk  = (const float*)d_in[7];
    const float* Wv  = (const float*)d_in[8];
    const float* bv  = (const float*)d_in[9];
    const float* Wp  = (const float*)d_in[10];
    const float* ub  = (const float*)d_in[11];
    const float* vb  = (const float*)d_in[12];
    const float* Wo1 = (const float*)d_in[13];
    const float* bo1 = (const float*)d_in[14];
    const float* Wo2 = (const float*)d_in[15];
    const float* bo2 = (const float*)d_in[16];
    float* out = (float*)d_out;

    float* scratch = nullptr;
    cudaGetSymbolAddress((void**)&scratch, g_scratch);

    const int attn_smem = 27492 * 4 + 1024;  // 110,992 B -> 2 blocks/SM
    cudaFuncSetAttribute(attn_kernel, cudaFuncAttributeMaxDynamicSharedMemorySize,
                         attn_smem);

    // batched projections (7 GEMMs in one launch)
    GDescArr pj{};
    pj.g[0] = { x1, Wq, bq, scratch + OFF_QU1, scratch + OFF_QV1, ub, vb, 2 };
    pj.g[1] = { x1, Wk, bk, scratch + OFF_K1,  nullptr, nullptr, nullptr, 1 };
    pj.g[2] = { x1, Wv, bv, scratch + OFF_V1,  nullptr, nullptr, nullptr, 1 };
    pj.g[3] = { x2, Wq, bq, scratch + OFF_QU2, scratch + OFF_QV2, ub, vb, 2 };
    pj.g[4] = { x2, Wk, bk, scratch + OFF_K2,  nullptr, nullptr, nullptr, 1 };
    pj.g[5] = { x2, Wv, bv, scratch + OFF_V2,  nullptr, nullptr, nullptr, 1 };
    pj.g[6] = { pe, Wp, nullptr, scratch + OFF_POS, nullptr, nullptr, nullptr, 1 };
    sgemm_batch<<<dim3(4, 32, 7), 256>>>(pj);

    // fused attention: tf32 scores + rel-shift(scatter) + softmax + ctx
    attn_kernel<<<dim3(64, 8, 8), 512, attn_smem>>>(scratch, mask, out);

    // batched output projections (2 GEMMs in one launch)
    GDescArr po{};
    po.g[0] = { scratch + OFF_CTX1, Wo1, bo1, out + OFF_CTX1OUT, nullptr, nullptr, nullptr, 0 };
    po.g[1] = { scratch + OFF_CTX2, Wo2, bo2, out + OFF_CTX2OUT, nullptr, nullptr, nullptr, 0 };
    sgemm_batch<<<dim3(4, 32, 2), 256>>>(po);
}

// round 14
// speedup vs baseline: 1.5279x; 1.5279x over previous
#include <cuda_runtime.h>
#include <math.h>

#define Bb 4
#define Ss 1024
#define Dd 512
#define Hh 8
#define DHd 64
#define SST 1034   // sbuf row stride (floats): conflict-free for 2/4-row strides

typedef unsigned long long ull;

__device__ __constant__ float kScale = 0.044194173824159216f; // 1/sqrt(512)

// ---- packed f32x2 helpers (sm_103a) ----
__device__ __forceinline__ ull pk2(float x, float y) {
    ull r; asm("mov.b64 %0, {%1, %2};" : "=l"(r) : "f"(x), "f"(y)); return r;
}
__device__ __forceinline__ ull splat2(float x) {
    ull r; asm("mov.b64 %0, {%1, %1};" : "=l"(r) : "f"(x)); return r;
}
__device__ __forceinline__ float lo2(ull v) { return __uint_as_float((unsigned)v); }
__device__ __forceinline__ float hi2(ull v) { return __uint_as_float((unsigned)(v >> 32)); }
__device__ __forceinline__ void fma2(ull& d, ull a, ull b) {
    asm("fma.rn.f32x2 %0, %1, %2, %0;" : "+l"(d) : "l"(a), "l"(b));
}
__device__ __forceinline__ float red2(ull v) { return lo2(v) + hi2(v); }

__device__ __forceinline__ unsigned smem_u32(const void* p) {
    return (unsigned)__cvta_generic_to_shared(p);
}
// volatile: real memory reads — must not be hoisted across C++ smem stores /
// __syncthreads() (R8 failure root cause).
__device__ __forceinline__ void lds2x64(ull& a, ull& b, unsigned addr) {
    asm volatile("ld.shared.v2.b64 {%0,%1}, [%2];" : "=l"(a), "=l"(b) : "r"(addr));
}
__device__ __forceinline__ float lds32(unsigned addr) {
    float v; asm volatile("ld.shared.f32 %0, [%1];" : "=f"(v) : "r"(addr)); return v;
}

// ---- tf32 mma helpers ----
__device__ __forceinline__ unsigned cvt_tf32(float x) {
    unsigned r; asm("cvt.rna.tf32.f32 %0, %1;" : "=r"(r) : "f"(x)); return r;
}
__device__ __forceinline__ void mma_tf32(
    float& d0, float& d1, float& d2, float& d3,
    unsigned a0, unsigned a1, unsigned a2, unsigned a3,
    unsigned b0, unsigned b1)
{
    asm volatile(
        "mma.sync.aligned.m16n8k8.row.col.f32.tf32.tf32.f32 "
        "{%0,%1,%2,%3}, {%4,%5,%6,%7}, {%8,%9}, {%0,%1,%2,%3};"
        : "+f"(d0), "+f"(d1), "+f"(d2), "+f"(d3)
        : "r"(a0), "r"(a1), "r"(a2), "r"(a3), "r"(b0), "r"(b1));
}

// scratch: 11 chunks of B*S*D floats
#define CHUNK ((size_t)Bb * Ss * Dd)  // 2097152
__device__ float g_scratch[CHUNK * 11];

#define OFF_QU1 (0 * CHUNK)
#define OFF_QV1 (1 * CHUNK)
#define OFF_K1  (2 * CHUNK)
#define OFF_V1  (3 * CHUNK)
#define OFF_QU2 (4 * CHUNK)
#define OFF_QV2 (5 * CHUNK)
#define OFF_K2  (6 * CHUNK)
#define OFF_V2  (7 * CHUNK)
#define OFF_POS (8 * CHUNK)
#define OFF_CTX1 (9 * CHUNK)
#define OFF_CTX2 (10 * CHUNK)

// d_out offsets (floats)
#define OFF_CTX1OUT ((size_t)0)
#define OFF_ATTN1   ((size_t)2097152)
#define OFF_CTX2OUT ((size_t)35651584)
#define OFF_ATTN2   ((size_t)37748736)

// ---------------------------------------------------------------------------
// Batched SGEMM (unchanged)
// ---------------------------------------------------------------------------
struct GDesc {
    const float* A; const float* W; const float* bias;
    float* d0; float* d1;
    const float* e0; const float* e1;
    long long mode;
};
struct GDescArr { GDesc g[8]; };

__global__ __launch_bounds__(256, 2)
void sgemm_batch(GDescArr P)
{
    GDesc gd = P.g[blockIdx.z];
    __shared__ float As[2][8][128];
    __shared__ float Bs[2][8][128];
    int tid = threadIdx.x;
    int tx = tid & 15, ty = tid >> 4;
    int bx = blockIdx.x, by = blockIdx.y;

    ull acc[8][4];
#pragma unroll
    for (int i = 0; i < 8; i++)
#pragma unroll
        for (int j = 0; j < 4; j++) acc[i][j] = 0ull;

    int arow = tid >> 1, ahalf = tid & 1;
    int bkr = tid >> 5, bn = tid & 31;
    const float* Aptr = gd.A + (size_t)(by * 128 + arow) * 512 + ahalf * 4;
    const float* Wptr = gd.W + (size_t)bkr * 512 + bx * 128 + bn * 4;

    float4 av = *(const float4*)(Aptr);
    float4 wv = *(const float4*)(Wptr);
    As[0][ahalf * 4 + 0][arow] = av.x;
    As[0][ahalf * 4 + 1][arow] = av.y;
    As[0][ahalf * 4 + 2][arow] = av.z;
    As[0][ahalf * 4 + 3][arow] = av.w;
    *(float4*)&Bs[0][bkr][bn * 4] = wv;
    __syncthreads();

#pragma unroll 1
    for (int kk = 0; kk < 64; kk++) {
        int buf = kk & 1;
        if (kk < 63) {
            av = *(const float4*)(Aptr + (kk + 1) * 8);
            wv = *(const float4*)(Wptr + (size_t)(kk + 1) * 8 * 512);
        }
#pragma unroll
        for (int k = 0; k < 8; k++) {
            float4 a0 = *(const float4*)&As[buf][k][ty * 8];
            float4 a1 = *(const float4*)&As[buf][k][ty * 8 + 4];
            unsigned bs_u = smem_u32(&Bs[buf][k][tx * 8]);
            ull bb[4];
            lds2x64(bb[0], bb[1], bs_u);
            lds2x64(bb[2], bb[3], bs_u + 16);
            ull aa[8] = { splat2(a0.x), splat2(a0.y), splat2(a0.z), splat2(a0.w),
                          splat2(a1.x), splat2(a1.y), splat2(a1.z), splat2(a1.w) };
#pragma unroll
            for (int i = 0; i < 8; i++)
#pragma unroll
                for (int j = 0; j < 4; j++) fma2(acc[i][j], aa[i], bb[j]);
        }
        if (kk < 63) {
            int nb = buf ^ 1;
            As[nb][ahalf * 4 + 0][arow] = av.x;
            As[nb][ahalf * 4 + 1][arow] = av.y;
            As[nb][ahalf * 4 + 2][arow] = av.z;
            As[nb][ahalf * 4 + 3][arow] = av.w;
            *(float4*)&Bs[nb][bkr][bn * 4] = wv;
            __syncthreads();
        }
    }

    int mode = (int)gd.mode;
#pragma unroll
    for (int i = 0; i < 8; i++) {
        int gr = by * 128 + ty * 8 + i;
#pragma unroll
        for (int jj = 0; jj < 4; jj++) {
#pragma unroll
            for (int half = 0; half < 2; half++) {
                int j = 2 * jj + half;
                int gc = bx * 128 + tx * 8 + j;
                float v = (half ? hi2(acc[i][jj]) : lo2(acc[i][jj]))
                          + (gd.bias ? gd.bias[gc] : 0.f);
                if (mode == 0) {
                    gd.d0[(size_t)gr * 512 + gc] = v;
                } else {
                    int h = gc >> 6, d = gc & 63;
                    int bI = gr >> 10, sI = gr & 1023;
                    size_t off = (((size_t)(bI * Hh + h) * Ss + sI) * DHd + d);
                    if (mode == 1) {
                        gd.d0[off] = v;
                    } else {
                        gd.d0[off] = v + gd.e0[gc];
                        gd.d1[off] = v + gd.e1[gc];
                    }
                }
            }
        }
    }
}

// ---------------------------------------------------------------------------
// Fused attention kernel (512 threads, ~111 KB smem -> 2 blocks/SM).
//  pass 1: sbuf = content scores via tf32 mma.sync (16x8x8 tiles)
//  pass 2: sbuf += pos scores (tf32 mma) scattered through rel-shift bijection
//  register softmax; attn to gmem; phase E: ctx = sbuf @ V (exact fp32)
// q buffers hold tf32-bit patterns (valid f32) -> raw u32 fragment loads.
// ---------------------------------------------------------------------------
__global__ __launch_bounds__(512, 2)
void attn_kernel(float* __restrict__ scratch,
                 const unsigned char* __restrict__ maskg,
                 float* __restrict__ out)
{
    extern __shared__ float sm[];
    float* qu   = sm;                 // [16][68] tf32-bit u32 (as float storage)
    float* qv   = sm + 1088;          // [17][68] tf32-bit u32
    float* kb   = sm + 2244;          // [128][68] = 8704 (tile / reduce buffer)
    float* sbuf = sm + 10948;         // [16][SST] = 16544 (scores -> probs)
    unsigned char* msk = (unsigned char*)(sm + 27492); // 1024 B

    int tid = threadIdx.x;
    int lane = tid & 31, w = tid >> 5;   // w 0..15
    int tile = blockIdx.x;   // 0..63
    int h = blockIdx.y;      // 0..7
    int bz = blockIdx.z;     // 0..7
    int bI = bz >> 1, st = bz & 1;

    const float* QUg = scratch + (st ? OFF_QU2 : OFF_QU1);
    const float* QVg = scratch + (st ? OFF_QV2 : OFF_QV1);
    const float* Kg  = scratch + (st ? OFF_K2  : OFF_K1);
    const float* Vg  = scratch + (st ? OFF_V2  : OFF_V1);
    const float* Pg  = scratch + OFF_POS;
    float* CTXg = scratch + (st ? OFF_CTX2 : OFF_CTX1);

    size_t bh = (size_t)(bI * Hh + h) * Ss * DHd;

    unsigned* quw = (unsigned*)qu;
    unsigned* qvw = (unsigned*)qv;

    // ---- phase 0: q loads pre-converted to tf32 bits, mask ----
#pragma unroll
    for (int it = 0; it < 2; it++) {
        int idx = it * 512 + tid;                // 0..1023
        int r = idx >> 6, d = idx & 63;
        quw[r * 68 + d] = cvt_tf32(QUg[bh + (size_t)(tile * 16 + r) * 64 + d]);
    }
#pragma unroll
    for (int it = 0; it < 3; it++) {
        int idx = it * 512 + tid;
        if (idx < 1088) {
            int r = idx >> 6, d = idx & 63;
            int gi = tile * 16 + r;
            if (gi > Ss - 1) gi = Ss - 1;        // row16 of last tile: blocked below
            qvw[r * 68 + d] = cvt_tf32(QVg[bh + (size_t)gi * 64 + d]);
        }
    }
    {
        const unsigned char* mrow = maskg + (size_t)bI * Ss;
#pragma unroll
        for (int it = 0; it < 2; it++) {
            int idx = it * 512 + tid;
            msk[idx] = mrow[idx];
        }
    }
    __syncthreads();

    unsigned qv_u = smem_u32(qv);
    unsigned kb_u = smem_u32(kb);

    int g  = lane >> 2;   // mma group 0..7
    int tg = lane & 3;    // thread-in-group 0..3

    // ================= pass 1: content -> sbuf (tf32 mma) =================
    {
        float4 fl[4];
#pragma unroll
        for (int it = 0; it < 4; it++) {
            int idx = it * 512 + tid; int s_ = idx >> 4, ds = idx & 15;
            fl[it] = *(const float4*)(Kg + bh + (size_t)s_ * 64 + ds * 4);
        }
#pragma unroll 1
        for (int c = 0; c < 8; c++) {
#pragma unroll
            for (int it = 0; it < 4; it++) {
                int idx = it * 512 + tid; int s_ = idx >> 4, ds = idx & 15;
                *(float4*)(kb + s_ * 68 + ds * 4) = fl[it];
            }
            __syncthreads();
            if (c < 7) {
#pragma unroll
                for (int it = 0; it < 4; it++) {
                    int idx = it * 512 + tid; int s_ = idx >> 4, ds = idx & 15;
                    fl[it] = *(const float4*)(Kg + bh
                                  + (size_t)((c + 1) * 128 + s_) * 64 + ds * 4);
                }
            }
            float d0 = 0.f, d1 = 0.f, d2 = 0.f, d3 = 0.f;
            const float* kcol = kb + (w * 8 + g) * 68;
#pragma unroll
            for (int ks = 0; ks < 8; ks++) {
                unsigned a0 = quw[g * 68 + ks * 8 + tg];
                unsigned a1 = quw[(g + 8) * 68 + ks * 8 + tg];
                unsigned a2 = quw[g * 68 + ks * 8 + tg + 4];
                unsigned a3 = quw[(g + 8) * 68 + ks * 8 + tg + 4];
                unsigned b0 = cvt_tf32(kcol[ks * 8 + tg]);
                unsigned b1 = cvt_tf32(kcol[ks * 8 + tg + 4]);
                mma_tf32(d0, d1, d2, d3, a0, a1, a2, a3, b0, b1);
            }
            int col = c * 128 + w * 8 + 2 * tg;
            *(float2*)&sbuf[g * SST + col] = make_float2(d0, d1);
            *(float2*)&sbuf[(g + 8) * SST + col] = make_float2(d2, d3);
            __syncthreads();
        }
    }

    // ================= pass 2: pos scatter-add into sbuf (tf32 mma) ========
    // raw pos[local row j, col cg], gg = tile*16+j:
    //   cg >= S-1-gg : sbuf[j][cg+gg+1-S] += v
    //   else (j>0)   : sbuf[j-1][cg+gg+1] += v
    {
        float4 fl[4];
#pragma unroll
        for (int it = 0; it < 4; it++) {
            int idx = it * 512 + tid; int s_ = idx >> 4, ds = idx & 15;
            fl[it] = *(const float4*)(Pg + bh + (size_t)s_ * 64 + ds * 4);
        }
#pragma unroll 1
        for (int c = 0; c < 8; c++) {
#pragma unroll
            for (int it = 0; it < 4; it++) {
                int idx = it * 512 + tid; int s_ = idx >> 4, ds = idx & 15;
                *(float4*)(kb + s_ * 68 + ds * 4) = fl[it];
            }
            __syncthreads();
            if (c < 7) {
#pragma unroll
                for (int it = 0; it < 4; it++) {
                    int idx = it * 512 + tid; int s_ = idx >> 4, ds = idx & 15;
                    fl[it] = *(const float4*)(Pg + bh
                                  + (size_t)((c + 1) * 128 + s_) * 64 + ds * 4);
                }
            }
            float d0 = 0.f, d1 = 0.f, d2 = 0.f, d3 = 0.f;
            const float* pcol = kb + (w * 8 + g) * 68;
#pragma unroll
            for (int ks = 0; ks < 8; ks++) {
                unsigned a0 = qvw[g * 68 + ks * 8 + tg];
                unsigned a1 = qvw[(g + 8) * 68 + ks * 8 + tg];
                unsigned a2 = qvw[g * 68 + ks * 8 + tg + 4];
                unsigned a3 = qvw[(g + 8) * 68 + ks * 8 + tg + 4];
                unsigned b0 = cvt_tf32(pcol[ks * 8 + tg]);
                unsigned b1 = cvt_tf32(pcol[ks * 8 + tg + 4]);
                mma_tf32(d0, d1, d2, d3, a0, a1, a2, a3, b0, b1);
            }
            int cg0 = c * 128 + w * 8 + 2 * tg;
            float vv[4] = { d0, d1, d2, d3 };
            int rr[4]   = { g, g, g + 8, g + 8 };
            int cc[4]   = { cg0, cg0 + 1, cg0, cg0 + 1 };
#pragma unroll
            for (int j = 0; j < 4; j++) {
                int row = rr[j], cg = cc[j];
                int gg = tile * 16 + row;
                bool condA = (cg >= Ss - 1 - gg);
                int addr = condA ? (row * SST + (cg + gg + 1 - Ss))
                                 : ((row - 1) * SST + (cg + gg + 1));
                if (condA || row > 0) sbuf[addr] += vv[j];
            }
            if (w < 4) {   // extra pos row 16 -> contributes only to row 15 (fp32)
                int col16 = w * 32 + lane;
                unsigned q16_u = qv_u + 16u * 272;
                unsigned pc_u = kb_u + (unsigned)col16 * 272;
                ull a = 0;
#pragma unroll
                for (int dq = 0; dq < 16; dq++) {
                    ull q01, q23; lds2x64(q01, q23, q16_u + dq * 16);
                    ull p01, p23; lds2x64(p01, p23, pc_u + dq * 16);
                    fma2(a, q01, p01); fma2(a, q23, p23);
                }
                int g16 = tile * 16 + 16;
                int cg16 = c * 128 + col16;
                if (g16 <= Ss - 1 && cg16 <= Ss - 2 - g16)
                    sbuf[15 * SST + (cg16 + g16 + 1)] += red2(a);
            }
            __syncthreads();
        }
    }

    // ---- softmax (warp = 1 row), register array ----
    int r = w;
    int ig = tile * 16 + r;
    float s[32];

    float mx = -1e30f;
#pragma unroll
    for (int jp = 0; jp < 32; jp++) {
        int t = jp * 32 + lane;
        float sc = sbuf[r * SST + t] * kScale;
        if (msk[t]) sc = -1e9f;
        s[jp] = sc;
        mx = fmaxf(mx, sc);
    }
#pragma unroll
    for (int o = 16; o > 0; o >>= 1)
        mx = fmaxf(mx, __shfl_xor_sync(0xffffffffu, mx, o));
    float sum = 0.f;
#pragma unroll
    for (int jp = 0; jp < 32; jp++) {
        float e = __expf(s[jp] - mx); s[jp] = e; sum += e;
    }
#pragma unroll
    for (int o = 16; o > 0; o >>= 1)
        sum += __shfl_xor_sync(0xffffffffu, sum, o);
    float inv = 1.f / sum;

    __syncthreads();

    size_t aout = (st ? OFF_ATTN2 : OFF_ATTN1) + ((size_t)(bI * Hh + h) * Ss) * Ss;
#pragma unroll
    for (int jp = 0; jp < 32; jp++) {
        int t = jp * 32 + lane;
        float p = s[jp] * inv;
        sbuf[r * SST + t] = p;
        out[aout + (size_t)ig * Ss + t] = p;
    }
    __syncthreads();

    // ---- phase E: ctx = sbuf(probs) @ V (exact fp32); kb tile/reduce buf ----
    {
        int dpg = tid & 15;        // d0 = dpg*4
        int rg  = (tid >> 4) & 7;  // rows rg*2, rg*2+1
        int tq  = tid >> 7;        // t-quarter 0..3
        int d0 = dpg * 4;

        ull e00 = 0, e01 = 0, e10 = 0, e11 = 0;

        float4 fl[4];
#pragma unroll
        for (int it = 0; it < 4; it++) {
            int idx = it * 512 + tid; int s_ = idx >> 4, ds = idx & 15;
            fl[it] = *(const float4*)(Vg + bh + (size_t)s_ * 64 + ds * 4);
        }
        unsigned pr_base = smem_u32(sbuf) + (unsigned)(rg * 2 * SST + tq * 32) * 4;
#pragma unroll 1
        for (int c = 0; c < 8; c++) {
#pragma unroll
            for (int it = 0; it < 4; it++) {
                int idx = it * 512 + tid; int s_ = idx >> 4, ds = idx & 15;
                *(float4*)(kb + s_ * 68 + ds * 4) = fl[it];
            }
            __syncthreads();
            if (c < 7) {
#pragma unroll
                for (int it = 0; it < 4; it++) {
                    int idx = it * 512 + tid; int s_ = idx >> 4, ds = idx & 15;
                    fl[it] = *(const float4*)(Vg + bh
                                  + (size_t)((c + 1) * 128 + s_) * 64 + ds * 4);
                }
            }
            unsigned v_base = kb_u + (unsigned)(tq * 32) * 272 + d0 * 4;
            unsigned pr_u = pr_base + (unsigned)(c * 128) * 4;
#pragma unroll
            for (int tt = 0; tt < 32; tt++) {
                ull v01, v23; lds2x64(v01, v23, v_base + tt * 272);
                float a0 = lds32(pr_u + tt * 4);
                float a1 = lds32(pr_u + tt * 4 + SST * 4);
                ull sx;
                sx = splat2(a0); fma2(e00, sx, v01); fma2(e01, sx, v23);
                sx = splat2(a1); fma2(e10, sx, v01); fma2(e11, sx, v23);
            }
            __syncthreads();
        }

        // partial sums -> kb[tq][row*64+d] (kb free now), reduce 4 quarters
        {
            float* red = kb + tq * 1024 + (rg * 2) * 64 + d0;
            float4 v0; v0.x = lo2(e00); v0.y = hi2(e00); v0.z = lo2(e01); v0.w = hi2(e01);
            float4 v1; v1.x = lo2(e10); v1.y = hi2(e10); v1.z = lo2(e11); v1.w = hi2(e11);
            *(float4*)(red) = v0;
            *(float4*)(red + 64) = v1;
        }
        __syncthreads();
        if (tid < 256) {
            int o = tid * 4;                  // 0..1023, 4 outputs per thread
            int row = o >> 6, dd = o & 63;
            float4 p0 = *(const float4*)(kb + 0 * 1024 + o);
            float4 p1 = *(const float4*)(kb + 1 * 1024 + o);
            float4 p2 = *(const float4*)(kb + 2 * 1024 + o);
            float4 p3 = *(const float4*)(kb + 3 * 1024 + o);
            float4 rr;
            rr.x = (p0.x + p1.x) + (p2.x + p3.x);
            rr.y = (p0.y + p1.y) + (p2.y + p3.y);
            rr.z = (p0.z + p1.z) + (p2.z + p3.z);
            rr.w = (p0.w + p1.w) + (p2.w + p3.w);
            int gi = tile * 16 + row;
            *(float4*)(CTXg + ((size_t)(bI * Ss + gi)) * Dd + h * DHd + dd) = rr;
        }
    }
}

// ---------------------------------------------------------------------------
extern "C" void kernel_launch(void* const* d_in, const int* in_sizes, int n_in,
                              void* d_out, int out_size)
{
    const float* x1  = (const float*)d_in[0];
    const float* x2  = (const float*)d_in[1];
    const float* pe  = (const float*)d_in[2];
    const unsigned char* mask = (const unsigned char*)d_in[3];
    const float* Wq  = (const float*)d_in[4];
    const float* bq  = (const float*)d_in[5];
    const float* Wk  = (const float*)d_in[6];
    const float* bk  = (const float*)d_in[7];
    const float* Wv  = (const float*)d_in[8];
    const float* bv  = (const float*)d_in[9];
    const float* Wp  = (const float*)d_in[10];
    const float* ub  = (const float*)d_in[11];
    const float* vb  = (const float*)d_in[12];
    const float* Wo1 = (const float*)d_in[13];
    const float* bo1 = (const float*)d_in[14];
    const float* Wo2 = (const float*)d_in[15];
    const float* bo2 = (const float*)d_in[16];
    float* out = (float*)d_out;

    float* scratch = nullptr;
    cudaGetSymbolAddress((void**)&scratch, g_scratch);

    const int attn_smem = 27492 * 4 + 1024;  // 110,992 B -> 2 blocks/SM
    cudaFuncSetAttribute(attn_kernel, cudaFuncAttributeMaxDynamicSharedMemorySize,
                         attn_smem);

    // batched projections (7 GEMMs in one launch)
    GDescArr pj{};
    pj.g[0] = { x1, Wq, bq, scratch + OFF_QU1, scratch + OFF_QV1, ub, vb, 2 };
    pj.g[1] = { x1, Wk, bk, scratch + OFF_K1,  nullptr, nullptr, nullptr, 1 };
    pj.g[2] = { x1, Wv, bv, scratch + OFF_V1,  nullptr, nullptr, nullptr, 1 };
    pj.g[3] = { x2, Wq, bq, scratch + OFF_QU2, scratch + OFF_QV2, ub, vb, 2 };
    pj.g[4] = { x2, Wk, bk, scratch + OFF_K2,  nullptr, nullptr, nullptr, 1 };
    pj.g[5] = { x2, Wv, bv, scratch + OFF_V2,  nullptr, nullptr, nullptr, 1 };
    pj.g[6] = { pe, Wp, nullptr, scratch + OFF_POS, nullptr, nullptr, nullptr, 1 };
    sgemm_batch<<<dim3(4, 32, 7), 256>>>(pj);

    // fused attention: tf32 scores + rel-shift(scatter) + softmax + ctx
    attn_kernel<<<dim3(64, 8, 8), 512, attn_smem>>>(scratch, mask, out);

    // batched output projections (2 GEMMs in one launch)
    GDescArr po{};
    po.g[0] = { scratch + OFF_CTX1, Wo1, bo1, out + OFF_CTX1OUT, nullptr, nullptr, nullptr, 0 };
    po.g[1] = { scratch + OFF_CTX2, Wo2, bo2, out + OFF_CTX2OUT, nullptr, nullptr, nullptr, 0 };
    sgemm_batch<<<dim3(4, 32, 2), 256>>>(po);
}

// round 15
// speedup vs baseline: 1.6960x; 1.1100x over previous
#include <cuda_runtime.h>
#include <math.h>

#define Bb 4
#define Ss 1024
#define Dd 512
#define Hh 8
#define DHd 64
#define SST 1034   // sbuf row stride (floats): conflict-free for 2/4-row strides

typedef unsigned long long ull;

__device__ __constant__ float kScale = 0.044194173824159216f; // 1/sqrt(512)

// ---- packed f32x2 helpers (sm_103a) ----
__device__ __forceinline__ ull pk2(float x, float y) {
    ull r; asm("mov.b64 %0, {%1, %2};" : "=l"(r) : "f"(x), "f"(y)); return r;
}
__device__ __forceinline__ ull splat2(float x) {
    ull r; asm("mov.b64 %0, {%1, %1};" : "=l"(r) : "f"(x)); return r;
}
__device__ __forceinline__ float lo2(ull v) { return __uint_as_float((unsigned)v); }
__device__ __forceinline__ float hi2(ull v) { return __uint_as_float((unsigned)(v >> 32)); }
__device__ __forceinline__ void fma2(ull& d, ull a, ull b) {
    asm("fma.rn.f32x2 %0, %1, %2, %0;" : "+l"(d) : "l"(a), "l"(b));
}
__device__ __forceinline__ float red2(ull v) { return lo2(v) + hi2(v); }

__device__ __forceinline__ unsigned smem_u32(const void* p) {
    return (unsigned)__cvta_generic_to_shared(p);
}
// volatile: real memory reads — must not be hoisted across C++ smem stores /
// __syncthreads() (R8 failure root cause).
__device__ __forceinline__ void lds2x64(ull& a, ull& b, unsigned addr) {
    asm volatile("ld.shared.v2.b64 {%0,%1}, [%2];" : "=l"(a), "=l"(b) : "r"(addr));
}
__device__ __forceinline__ float lds32(unsigned addr) {
    float v; asm volatile("ld.shared.f32 %0, [%1];" : "=f"(v) : "r"(addr)); return v;
}

// ---- tf32 mma helpers ----
__device__ __forceinline__ unsigned cvt_tf32(float x) {
    unsigned r; asm("cvt.rna.tf32.f32 %0, %1;" : "=r"(r) : "f"(x)); return r;
}
__device__ __forceinline__ void mma_tf32(
    float& d0, float& d1, float& d2, float& d3,
    unsigned a0, unsigned a1, unsigned a2, unsigned a3,
    unsigned b0, unsigned b1)
{
    asm volatile(
        "mma.sync.aligned.m16n8k8.row.col.f32.tf32.tf32.f32 "
        "{%0,%1,%2,%3}, {%4,%5,%6,%7}, {%8,%9}, {%0,%1,%2,%3};"
        : "+f"(d0), "+f"(d1), "+f"(d2), "+f"(d3)
        : "r"(a0), "r"(a1), "r"(a2), "r"(a3), "r"(b0), "r"(b1));
}

// scratch: 11 chunks of B*S*D floats
#define CHUNK ((size_t)Bb * Ss * Dd)  // 2097152
__device__ float g_scratch[CHUNK * 11];

#define OFF_QU1 (0 * CHUNK)
#define OFF_QV1 (1 * CHUNK)
#define OFF_K1  (2 * CHUNK)
#define OFF_V1  (3 * CHUNK)
#define OFF_QU2 (4 * CHUNK)
#define OFF_QV2 (5 * CHUNK)
#define OFF_K2  (6 * CHUNK)
#define OFF_V2  (7 * CHUNK)
#define OFF_POS (8 * CHUNK)
#define OFF_CTX1 (9 * CHUNK)
#define OFF_CTX2 (10 * CHUNK)

// d_out offsets (floats)
#define OFF_CTX1OUT ((size_t)0)
#define OFF_ATTN1   ((size_t)2097152)
#define OFF_CTX2OUT ((size_t)35651584)
#define OFF_ATTN2   ((size_t)37748736)

// ---------------------------------------------------------------------------
// Batched SGEMM (unchanged)
// ---------------------------------------------------------------------------
struct GDesc {
    const float* A; const float* W; const float* bias;
    float* d0; float* d1;
    const float* e0; const float* e1;
    long long mode;
};
struct GDescArr { GDesc g[8]; };

__global__ __launch_bounds__(256, 2)
void sgemm_batch(GDescArr P)
{
    GDesc gd = P.g[blockIdx.z];
    __shared__ float As[2][8][128];
    __shared__ float Bs[2][8][128];
    int tid = threadIdx.x;
    int tx = tid & 15, ty = tid >> 4;
    int bx = blockIdx.x, by = blockIdx.y;

    ull acc[8][4];
#pragma unroll
    for (int i = 0; i < 8; i++)
#pragma unroll
        for (int j = 0; j < 4; j++) acc[i][j] = 0ull;

    int arow = tid >> 1, ahalf = tid & 1;
    int bkr = tid >> 5, bn = tid & 31;
    const float* Aptr = gd.A + (size_t)(by * 128 + arow) * 512 + ahalf * 4;
    const float* Wptr = gd.W + (size_t)bkr * 512 + bx * 128 + bn * 4;

    float4 av = *(const float4*)(Aptr);
    float4 wv = *(const float4*)(Wptr);
    As[0][ahalf * 4 + 0][arow] = av.x;
    As[0][ahalf * 4 + 1][arow] = av.y;
    As[0][ahalf * 4 + 2][arow] = av.z;
    As[0][ahalf * 4 + 3][arow] = av.w;
    *(float4*)&Bs[0][bkr][bn * 4] = wv;
    __syncthreads();

#pragma unroll 1
    for (int kk = 0; kk < 64; kk++) {
        int buf = kk & 1;
        if (kk < 63) {
            av = *(const float4*)(Aptr + (kk + 1) * 8);
            wv = *(const float4*)(Wptr + (size_t)(kk + 1) * 8 * 512);
        }
#pragma unroll
        for (int k = 0; k < 8; k++) {
            float4 a0 = *(const float4*)&As[buf][k][ty * 8];
            float4 a1 = *(const float4*)&As[buf][k][ty * 8 + 4];
            unsigned bs_u = smem_u32(&Bs[buf][k][tx * 8]);
            ull bb[4];
            lds2x64(bb[0], bb[1], bs_u);
            lds2x64(bb[2], bb[3], bs_u + 16);
            ull aa[8] = { splat2(a0.x), splat2(a0.y), splat2(a0.z), splat2(a0.w),
                          splat2(a1.x), splat2(a1.y), splat2(a1.z), splat2(a1.w) };
#pragma unroll
            for (int i = 0; i < 8; i++)
#pragma unroll
                for (int j = 0; j < 4; j++) fma2(acc[i][j], aa[i], bb[j]);
        }
        if (kk < 63) {
            int nb = buf ^ 1;
            As[nb][ahalf * 4 + 0][arow] = av.x;
            As[nb][ahalf * 4 + 1][arow] = av.y;
            As[nb][ahalf * 4 + 2][arow] = av.z;
            As[nb][ahalf * 4 + 3][arow] = av.w;
            *(float4*)&Bs[nb][bkr][bn * 4] = wv;
            __syncthreads();
        }
    }

    int mode = (int)gd.mode;
#pragma unroll
    for (int i = 0; i < 8; i++) {
        int gr = by * 128 + ty * 8 + i;
#pragma unroll
        for (int jj = 0; jj < 4; jj++) {
#pragma unroll
            for (int half = 0; half < 2; half++) {
                int j = 2 * jj + half;
                int gc = bx * 128 + tx * 8 + j;
                float v = (half ? hi2(acc[i][jj]) : lo2(acc[i][jj]))
                          + (gd.bias ? gd.bias[gc] : 0.f);
                if (mode == 0) {
                    gd.d0[(size_t)gr * 512 + gc] = v;
                } else {
                    int h = gc >> 6, d = gc & 63;
                    int bI = gr >> 10, sI = gr & 1023;
                    size_t off = (((size_t)(bI * Hh + h) * Ss + sI) * DHd + d);
                    if (mode == 1) {
                        gd.d0[off] = v;
                    } else {
                        gd.d0[off] = v + gd.e0[gc];
                        gd.d1[off] = v + gd.e1[gc];
                    }
                }
            }
        }
    }
}

// ---------------------------------------------------------------------------
// Fused attention kernel (512 threads, ~111 KB smem -> 2 blocks/SM).
//  pass 1: sbuf = content scores via tf32 mma.sync
//  pass 2: sbuf += pos scores (tf32 mma) scattered through rel-shift bijection
//  register softmax; attn(fp32) to gmem; probs re-stored as tf32 bits in sbuf
//  phase E: ctx = probs @ V via tf32 mma (k-split across warp halves)
// ---------------------------------------------------------------------------
__global__ __launch_bounds__(512, 2)
void attn_kernel(float* __restrict__ scratch,
                 const unsigned char* __restrict__ maskg,
                 float* __restrict__ out)
{
    extern __shared__ float sm[];
    float* qu   = sm;                 // [16][68] tf32-bit u32 (as float storage)
    float* qv   = sm + 1088;          // [17][68] tf32-bit u32
    float* kb   = sm + 2244;          // [128][68] = 8704 (tile / reduce buffer)
    float* sbuf = sm + 10948;         // [16][SST] = 16544 (scores -> prob bits)
    unsigned char* msk = (unsigned char*)(sm + 27492); // 1024 B

    int tid = threadIdx.x;
    int lane = tid & 31, w = tid >> 5;   // w 0..15
    int tile = blockIdx.x;   // 0..63
    int h = blockIdx.y;      // 0..7
    int bz = blockIdx.z;     // 0..7
    int bI = bz >> 1, st = bz & 1;

    const float* QUg = scratch + (st ? OFF_QU2 : OFF_QU1);
    const float* QVg = scratch + (st ? OFF_QV2 : OFF_QV1);
    const float* Kg  = scratch + (st ? OFF_K2  : OFF_K1);
    const float* Vg  = scratch + (st ? OFF_V2  : OFF_V1);
    const float* Pg  = scratch + OFF_POS;
    float* CTXg = scratch + (st ? OFF_CTX2 : OFF_CTX1);

    size_t bh = (size_t)(bI * Hh + h) * Ss * DHd;

    unsigned* quw = (unsigned*)qu;
    unsigned* qvw = (unsigned*)qv;

    // ---- phase 0: q loads pre-converted to tf32 bits, mask ----
#pragma unroll
    for (int it = 0; it < 2; it++) {
        int idx = it * 512 + tid;                // 0..1023
        int r = idx >> 6, d = idx & 63;
        quw[r * 68 + d] = cvt_tf32(QUg[bh + (size_t)(tile * 16 + r) * 64 + d]);
    }
#pragma unroll
    for (int it = 0; it < 3; it++) {
        int idx = it * 512 + tid;
        if (idx < 1088) {
            int r = idx >> 6, d = idx & 63;
            int gi = tile * 16 + r;
            if (gi > Ss - 1) gi = Ss - 1;        // row16 of last tile: blocked below
            qvw[r * 68 + d] = cvt_tf32(QVg[bh + (size_t)gi * 64 + d]);
        }
    }
    {
        const unsigned char* mrow = maskg + (size_t)bI * Ss;
#pragma unroll
        for (int it = 0; it < 2; it++) {
            int idx = it * 512 + tid;
            msk[idx] = mrow[idx];
        }
    }
    __syncthreads();

    unsigned qv_u = smem_u32(qv);
    unsigned kb_u = smem_u32(kb);

    int g  = lane >> 2;   // mma group 0..7
    int tg = lane & 3;    // thread-in-group 0..3

    // ================= pass 1: content -> sbuf (tf32 mma) =================
    {
        float4 fl[4];
#pragma unroll
        for (int it = 0; it < 4; it++) {
            int idx = it * 512 + tid; int s_ = idx >> 4, ds = idx & 15;
            fl[it] = *(const float4*)(Kg + bh + (size_t)s_ * 64 + ds * 4);
        }
#pragma unroll 1
        for (int c = 0; c < 8; c++) {
#pragma unroll
            for (int it = 0; it < 4; it++) {
                int idx = it * 512 + tid; int s_ = idx >> 4, ds = idx & 15;
                *(float4*)(kb + s_ * 68 + ds * 4) = fl[it];
            }
            __syncthreads();
            if (c < 7) {
#pragma unroll
                for (int it = 0; it < 4; it++) {
                    int idx = it * 512 + tid; int s_ = idx >> 4, ds = idx & 15;
                    fl[it] = *(const float4*)(Kg + bh
                                  + (size_t)((c + 1) * 128 + s_) * 64 + ds * 4);
                }
            }
            float d0 = 0.f, d1 = 0.f, d2 = 0.f, d3 = 0.f;
            const float* kcol = kb + (w * 8 + g) * 68;
#pragma unroll
            for (int ks = 0; ks < 8; ks++) {
                unsigned a0 = quw[g * 68 + ks * 8 + tg];
                unsigned a1 = quw[(g + 8) * 68 + ks * 8 + tg];
                unsigned a2 = quw[g * 68 + ks * 8 + tg + 4];
                unsigned a3 = quw[(g + 8) * 68 + ks * 8 + tg + 4];
                unsigned b0 = cvt_tf32(kcol[ks * 8 + tg]);
                unsigned b1 = cvt_tf32(kcol[ks * 8 + tg + 4]);
                mma_tf32(d0, d1, d2, d3, a0, a1, a2, a3, b0, b1);
            }
            int col = c * 128 + w * 8 + 2 * tg;
            *(float2*)&sbuf[g * SST + col] = make_float2(d0, d1);
            *(float2*)&sbuf[(g + 8) * SST + col] = make_float2(d2, d3);
            __syncthreads();
        }
    }

    // ================= pass 2: pos scatter-add into sbuf (tf32 mma) ========
    // raw pos[local row j, col cg], gg = tile*16+j:
    //   cg >= S-1-gg : sbuf[j][cg+gg+1-S] += v
    //   else (j>0)   : sbuf[j-1][cg+gg+1] += v
    {
        float4 fl[4];
#pragma unroll
        for (int it = 0; it < 4; it++) {
            int idx = it * 512 + tid; int s_ = idx >> 4, ds = idx & 15;
            fl[it] = *(const float4*)(Pg + bh + (size_t)s_ * 64 + ds * 4);
        }
#pragma unroll 1
        for (int c = 0; c < 8; c++) {
#pragma unroll
            for (int it = 0; it < 4; it++) {
                int idx = it * 512 + tid; int s_ = idx >> 4, ds = idx & 15;
                *(float4*)(kb + s_ * 68 + ds * 4) = fl[it];
            }
            __syncthreads();
            if (c < 7) {
#pragma unroll
                for (int it = 0; it < 4; it++) {
                    int idx = it * 512 + tid; int s_ = idx >> 4, ds = idx & 15;
                    fl[it] = *(const float4*)(Pg + bh
                                  + (size_t)((c + 1) * 128 + s_) * 64 + ds * 4);
                }
            }
            float d0 = 0.f, d1 = 0.f, d2 = 0.f, d3 = 0.f;
            const float* pcol = kb + (w * 8 + g) * 68;
#pragma unroll
            for (int ks = 0; ks < 8; ks++) {
                unsigned a0 = qvw[g * 68 + ks * 8 + tg];
                unsigned a1 = qvw[(g + 8) * 68 + ks * 8 + tg];
                unsigned a2 = qvw[g * 68 + ks * 8 + tg + 4];
                unsigned a3 = qvw[(g + 8) * 68 + ks * 8 + tg + 4];
                unsigned b0 = cvt_tf32(pcol[ks * 8 + tg]);
                unsigned b1 = cvt_tf32(pcol[ks * 8 + tg + 4]);
                mma_tf32(d0, d1, d2, d3, a0, a1, a2, a3, b0, b1);
            }
            int cg0 = c * 128 + w * 8 + 2 * tg;
            float vv[4] = { d0, d1, d2, d3 };
            int rr[4]   = { g, g, g + 8, g + 8 };
            int cc[4]   = { cg0, cg0 + 1, cg0, cg0 + 1 };
#pragma unroll
            for (int j = 0; j < 4; j++) {
                int row = rr[j], cg = cc[j];
                int gg = tile * 16 + row;
                bool condA = (cg >= Ss - 1 - gg);
                int addr = condA ? (row * SST + (cg + gg + 1 - Ss))
                                 : ((row - 1) * SST + (cg + gg + 1));
                if (condA || row > 0) sbuf[addr] += vv[j];
            }
            if (w < 4) {   // extra pos row 16 -> contributes only to row 15 (fp32)
                int col16 = w * 32 + lane;
                unsigned q16_u = qv_u + 16u * 272;
                unsigned pc_u = kb_u + (unsigned)col16 * 272;
                ull a = 0;
#pragma unroll
                for (int dq = 0; dq < 16; dq++) {
                    ull q01, q23; lds2x64(q01, q23, q16_u + dq * 16);
                    ull p01, p23; lds2x64(p01, p23, pc_u + dq * 16);
                    fma2(a, q01, p01); fma2(a, q23, p23);
                }
                int g16 = tile * 16 + 16;
                int cg16 = c * 128 + col16;
                if (g16 <= Ss - 1 && cg16 <= Ss - 2 - g16)
                    sbuf[15 * SST + (cg16 + g16 + 1)] += red2(a);
            }
            __syncthreads();
        }
    }

    // ---- softmax (warp = 1 row), register array ----
    int r = w;
    int ig = tile * 16 + r;
    float s[32];

    float mx = -1e30f;
#pragma unroll
    for (int jp = 0; jp < 32; jp++) {
        int t = jp * 32 + lane;
        float sc = sbuf[r * SST + t] * kScale;
        if (msk[t]) sc = -1e9f;
        s[jp] = sc;
        mx = fmaxf(mx, sc);
    }
#pragma unroll
    for (int o = 16; o > 0; o >>= 1)
        mx = fmaxf(mx, __shfl_xor_sync(0xffffffffu, mx, o));
    float sum = 0.f;
#pragma unroll
    for (int jp = 0; jp < 32; jp++) {
        float e = __expf(s[jp] - mx); s[jp] = e; sum += e;
    }
#pragma unroll
    for (int o = 16; o > 0; o >>= 1)
        sum += __shfl_xor_sync(0xffffffffu, sum, o);
    float inv = 1.f / sum;

    __syncthreads();

    // ---- phase D: fp32 probs to gmem; tf32-bit probs into sbuf ----
    size_t aout = (st ? OFF_ATTN2 : OFF_ATTN1) + ((size_t)(bI * Hh + h) * Ss) * Ss;
    unsigned* sbw = (unsigned*)sbuf;
#pragma unroll
    for (int jp = 0; jp < 32; jp++) {
        int t = jp * 32 + lane;
        float p = s[jp] * inv;
        out[aout + (size_t)ig * Ss + t] = p;
        sbw[r * SST + t] = cvt_tf32(p);
    }
    __syncthreads();

    // ---- phase E: ctx = probs @ V via tf32 mma ----
    // warp w: cols nbase=(w&7)*8, k-half kh=w>>3 (t-subrange kh*64 within tile)
    {
        int nbase = (w & 7) * 8;
        int kh = w >> 3;

        float d0 = 0.f, d1 = 0.f, d2 = 0.f, d3 = 0.f;

        float4 fl[4];
#pragma unroll
        for (int it = 0; it < 4; it++) {
            int idx = it * 512 + tid; int s_ = idx >> 4, ds = idx & 15;
            fl[it] = *(const float4*)(Vg + bh + (size_t)s_ * 64 + ds * 4);
        }
#pragma unroll 1
        for (int c = 0; c < 8; c++) {
#pragma unroll
            for (int it = 0; it < 4; it++) {
                int idx = it * 512 + tid; int s_ = idx >> 4, ds = idx & 15;
                *(float4*)(kb + s_ * 68 + ds * 4) = fl[it];
            }
            __syncthreads();
            if (c < 7) {
#pragma unroll
                for (int it = 0; it < 4; it++) {
                    int idx = it * 512 + tid; int s_ = idx >> 4, ds = idx & 15;
                    fl[it] = *(const float4*)(Vg + bh
                                  + (size_t)((c + 1) * 128 + s_) * 64 + ds * 4);
                }
            }
            int cbase = c * 128 + kh * 64;
            const float* vb2 = kb + (kh * 64) * 68 + nbase + g;
#pragma unroll
            for (int ks = 0; ks < 8; ks++) {
                int t0 = ks * 8;
                unsigned a0 = sbw[g * SST + cbase + t0 + tg];
                unsigned a1 = sbw[(g + 8) * SST + cbase + t0 + tg];
                unsigned a2 = sbw[g * SST + cbase + t0 + tg + 4];
                unsigned a3 = sbw[(g + 8) * SST + cbase + t0 + tg + 4];
                unsigned b0 = cvt_tf32(vb2[(t0 + tg) * 68]);
                unsigned b1 = cvt_tf32(vb2[(t0 + tg + 4) * 68]);
                mma_tf32(d0, d1, d2, d3, a0, a1, a2, a3, b0, b1);
            }
            __syncthreads();
        }

        // partials -> kb[kh][row][col] (stride 68), then 2-way reduce
        {
            float* red = kb + kh * 1100;
            *(float2*)&red[g * 68 + nbase + 2 * tg] = make_float2(d0, d1);
            *(float2*)&red[(g + 8) * 68 + nbase + 2 * tg] = make_float2(d2, d3);
        }
        __syncthreads();
        {
            int o = tid * 2;                  // 0..1022, 2 outputs per thread
            int row = o >> 6, dd = o & 63;
            float2 p0 = *(const float2*)&kb[row * 68 + dd];
            float2 p1 = *(const float2*)&kb[1100 + row * 68 + dd];
            float2 rr2 = make_float2(p0.x + p1.x, p0.y + p1.y);
            int gi = tile * 16 + row;
            *(float2*)(CTXg + ((size_t)(bI * Ss + gi)) * Dd + h * DHd + dd) = rr2;
        }
    }
}

// ---------------------------------------------------------------------------
extern "C" void kernel_launch(void* const* d_in, const int* in_sizes, int n_in,
                              void* d_out, int out_size)
{
    const float* x1  = (const float*)d_in[0];
    const float* x2  = (const float*)d_in[1];
    const float* pe  = (const float*)d_in[2];
    const unsigned char* mask = (const unsigned char*)d_in[3];
    const float* Wq  = (const float*)d_in[4];
    const float* bq  = (const float*)d_in[5];
    const float* Wk  = (const float*)d_in[6];
    const float* bk  = (const float*)d_in[7];
    const float* Wv  = (const float*)d_in[8];
    const float* bv  = (const float*)d_in[9];
    const float* Wp  = (const float*)d_in[10];
    const float* ub  = (const float*)d_in[11];
    const float* vb  = (const float*)d_in[12];
    const float* Wo1 = (const float*)d_in[13];
    const float* bo1 = (const float*)d_in[14];
    const float* Wo2 = (const float*)d_in[15];
    const float* bo2 = (const float*)d_in[16];
    float* out = (float*)d_out;

    float* scratch = nullptr;
    cudaGetSymbolAddress((void**)&scratch, g_scratch);

    const int attn_smem = 27492 * 4 + 1024;  // 110,992 B -> 2 blocks/SM
    cudaFuncSetAttribute(attn_kernel, cudaFuncAttributeMaxDynamicSharedMemorySize,
                         attn_smem);

    // batched projections (7 GEMMs in one launch)
    GDescArr pj{};
    pj.g[0] = { x1, Wq, bq, scratch + OFF_QU1, scratch + OFF_QV1, ub, vb, 2 };
    pj.g[1] = { x1, Wk, bk, scratch + OFF_K1,  nullptr, nullptr, nullptr, 1 };
    pj.g[2] = { x1, Wv, bv, scratch + OFF_V1,  nullptr, nullptr, nullptr, 1 };
    pj.g[3] = { x2, Wq, bq, scratch + OFF_QU2, scratch + OFF_QV2, ub, vb, 2 };
    pj.g[4] = { x2, Wk, bk, scratch + OFF_K2,  nullptr, nullptr, nullptr, 1 };
    pj.g[5] = { x2, Wv, bv, scratch + OFF_V2,  nullptr, nullptr, nullptr, 1 };
    pj.g[6] = { pe, Wp, nullptr, scratch + OFF_POS, nullptr, nullptr, nullptr, 1 };
    sgemm_batch<<<dim3(4, 32, 7), 256>>>(pj);

    // fused attention: tf32 scores + rel-shift(scatter) + softmax + tf32 ctx
    attn_kernel<<<dim3(64, 8, 8), 512, attn_smem>>>(scratch, mask, out);

    // batched output projections (2 GEMMs in one launch)
    GDescArr po{};
    po.g[0] = { scratch + OFF_CTX1, Wo1, bo1, out + OFF_CTX1OUT, nullptr, nullptr, nullptr, 0 };
    po.g[1] = { scratch + OFF_CTX2, Wo2, bo2, out + OFF_CTX2OUT, nullptr, nullptr, nullptr, 0 };
    sgemm_batch<<<dim3(4, 32, 2), 256>>>(po);
}